// round 12
// baseline (speedup 1.0000x reference)
#include <cuda_runtime.h>
#include <cstdint>
#include <math.h>

// ---------------- problem constants ----------------
#define BATCH   4
#define NPIX    2048
#define NBINS   4096
#define KT      250
#define NREP    64
#define TSIM    3846          // (NBINS - KT + 1) - 1
#define NCHAIN  (BATCH*NREP)  // 256
#define TPAD    3872
#define PCHUNKS 16
#define PPER    (NPIX/PCHUNKS) // 128
#define NCHUNK  ((TSIM + 31) / 32)   // 121
#define FPAD    40

// ---------------- scratch (no allocations allowed) ----------------
__device__ float    d_partial[PCHUNKS][BATCH*NBINS]; // 1 MiB
__device__ float    d_g[BATCH*TPAD];                 // gensig (padding stays 0)
__device__ float    d_C[NCHAIN*TPAD];                // logit thresholds (padding stays 0)

// ---------------- threefry2x32 (JAX constants, 20 rounds) ----------------
__device__ __forceinline__ void tf2x32(uint32_t k0, uint32_t k1,
                                       uint32_t x0, uint32_t x1,
                                       uint32_t &o0, uint32_t &o1) {
    uint32_t k2 = k0 ^ k1 ^ 0x1BD11BDAu;
#define ROTL(v,s) (((v)<<(s))|((v)>>(32-(s))))
#define RND(r) { x0 += x1; x1 = ROTL(x1,(r)); x1 ^= x0; }
    x0 += k0; x1 += k1;
    RND(13) RND(15) RND(26) RND(6)
    x0 += k1; x1 += k2 + 1u;
    RND(17) RND(29) RND(16) RND(24)
    x0 += k2; x1 += k0 + 2u;
    RND(13) RND(15) RND(26) RND(6)
    x0 += k0; x1 += k1 + 3u;
    RND(17) RND(29) RND(16) RND(24)
    x0 += k1; x1 += k2 + 4u;
    RND(13) RND(15) RND(26) RND(6)
    x0 += k2; x1 += k0 + 5u;
    o0 = x0; o1 = x1;
#undef RND
#undef ROTL
}

// ---------------- K1: spatial projection partials ----------------
// Scalar per-thread: grid (32,16,4), block 128 -> high occupancy, same per-t order.
__global__ void k_proj(const float* __restrict__ stim, const float* __restrict__ w) {
    int b  = blockIdx.z;
    int pc = blockIdx.y;
    int t  = blockIdx.x * 128 + threadIdx.x;
    const float* base = stim + ((size_t)b * NPIX + (size_t)pc * PPER) * NBINS + t;

    __shared__ float ws[PPER];
    if (threadIdx.x < PPER) ws[threadIdx.x] = w[pc * PPER + threadIdx.x];
    __syncthreads();

    float acc = 0.0f;
#pragma unroll 16
    for (int p = 0; p < PPER; ++p)
        acc += ws[p] * base[(size_t)p * NBINS];
    d_partial[pc][b * NBINS + t] = acc;
}

// ---------------- K2: reduce partials + temporal conv (fp64, 8 accumulators) ----------------
#define CCH 121
__global__ void k_conv(const float* __restrict__ tc, const float* __restrict__ bias) {
    int b  = blockIdx.y;
    int t0 = blockIdx.x * CCH;
    int cnt = min(CCH, TSIM - t0);
    if (cnt <= 0) return;
    int need = cnt + KT - 1;

    __shared__ float sps[CCH + KT];
    __shared__ float tcs[KT + 6];
    for (int i = threadIdx.x; i < need; i += blockDim.x) {
        float s = 0.f;
        int idx = b * NBINS + t0 + i;
#pragma unroll
        for (int pc = 0; pc < PCHUNKS; ++pc) s += d_partial[pc][idx];
        sps[i] = s;
    }
    for (int i = threadIdx.x; i < KT + 6; i += blockDim.x) tcs[i] = (i < KT) ? tc[i] : 0.0f;
    __syncthreads();

    double bs = (double)bias[0];
    for (int t = threadIdx.x; t < cnt; t += blockDim.x) {
        double a[8];
#pragma unroll
        for (int j = 0; j < 8; ++j) a[j] = 0.0;
#pragma unroll 4
        for (int k = 0; k < KT; k += 8) {
#pragma unroll
            for (int j = 0; j < 8; ++j)
                if (k + j < KT) a[j] += (double)sps[t + k + j] * (double)tcs[k + j];
        }
        double s = ((a[0] + a[1]) + (a[2] + a[3])) + ((a[4] + a[5]) + (a[6] + a[7]));
        d_g[b * TPAD + t0 + t] = (float)(s + bs);
    }
}

// ---------------- double-float fp32 log of exact-integer-valued float ----------------
__device__ __forceinline__ void df_logm(float a, float &lh, float &ll, int &e) {
    int ib = __float_as_int(a);
    e = ((ib >> 23) & 0xff) - 127;
    float m = __int_as_float((ib & 0x007fffff) | 0x3f800000);
    if (m > 1.5f) { m *= 0.5f; e += 1; }
    float num = m - 1.0f;
    float dh  = m + 1.0f;
    float bv  = dh - m;
    float dl  = (1.0f - bv) + (m - (dh - bv));
    float q1  = __fdividef(num, dh);
    float rem = fmaf(-q1, dh, num);
    rem       = fmaf(-q1, dl, rem);
    float q2  = __fdividef(rem, dh);
    float sh  = q1 + q2;
    float sl  = q2 - (sh - q1);
    float t = sh * sh;
    float w = fmaf(t, 1.0f/19.0f, 1.0f/17.0f);
    w = fmaf(t, w, 1.0f/15.0f);
    w = fmaf(t, w, 1.0f/13.0f);
    w = fmaf(t, w, 1.0f/11.0f);
    w = fmaf(t, w, 1.0f/9.0f);
    w = fmaf(t, w, 1.0f/7.0f);
    w = fmaf(t, w, 1.0f/5.0f);
    w = fmaf(t, w, 1.0f/3.0f);
    w = w * t;
    float ph = 2.0f * sh, pl = 2.0f * sl;
    float qh = ph * w;
    float ql = fmaf(ph, w, -qh);
    ql = fmaf(pl, w, ql);
    lh = ph + qh;
    ll = ((ph - lh) + qh) + (pl + ql);
}

// ---------------- K3: keys + thresholds fused. c[i][t] = logit(uniform) ----------------
// grid (16, 64), block 256: each thread owns one t, 4 chains.
__global__ void k_thresh() {
    int t = blockIdx.x * 256 + threadIdx.x;
    if (t >= TSIM) return;
    uint32_t kk0, kk1;
    tf2x32(0u, 42u, 0u, (uint32_t)t, kk0, kk1);   // split(key(42))[t]
    int i0 = blockIdx.y * 4;
#pragma unroll
    for (int j = 0; j < 4; ++j) {
        int i = i0 + j;
        uint32_t o0, o1;
        tf2x32(kk0, kk1, 0u, (uint32_t)i, o0, o1);
        uint32_t bits = o0 ^ o1;
        uint32_t k = bits >> 9;
        float c;
        if (k == 0u) {
            c = -__int_as_float(0x7f800000);
        } else {
            float a = (float)k;
            float bf = (float)(0x800000u - k);
            float lah, lal; int ea; df_logm(a,  lah, lal, ea);
            float lbh, lbl; int eb; df_logm(bf, lbh, lbl, eb);
            float de = (float)(ea - eb);
            const float L2H = 0.693145751953125f;
            const float L2L = 1.42860682e-6f;
            float s   = lah - lbh;
            float bv2 = s - lah;
            float err = (lah - (s - bv2)) + ((-lbh) - bv2);
            float dl2 = err + (lal - lbl);
            float Eh  = de * L2H;
            float th2 = Eh + s;
            float bv3 = th2 - Eh;
            float err2 = (Eh - (th2 - bv3)) + (s - bv3);
            c = th2 + (err2 + dl2 + de * L2L);
        }
        d_C[i * TPAD + t] = c;
    }
}

// ---------------- K4: simulation (R10-proven) ----------------
// warp 0 = consumer (sign+LOP3 select chain), warps 1-4 = ybase producers.
__global__ void __launch_bounds__(160, 2)
k_sim(const float* __restrict__ initial, const float* __restrict__ fbfilt,
      float* __restrict__ out) {
    int chain = blockIdx.x;          // b*64 + r
    int b     = chain >> 6;
    int tid   = threadIdx.x;
    int lane  = tid & 31;
    int warp  = tid >> 5;

    __shared__ float histbuf[8 + KT + TSIM + 40];
    __shared__ float fsnp[FPAD + 256];     // NEGATED padded feedback filter
    __shared__ float ybuf[2][32];          // double-buffered ybase = c - g + far(negated)

    float* hist = histbuf + 8;
    const float* ip = initial + b * KT;

    for (int k = tid; k < FPAD + 256; k += 160) {
        int i = k - FPAD;
        fsnp[k] = (i >= 0 && i < KT) ? -fbfilt[i] : 0.0f;
    }
    for (int k = tid; k < 8; k += 160) histbuf[k] = 0.0f;
    for (int k = tid; k < KT; k += 160) {
        float v = ip[k];
        hist[k] = v;
        out[(size_t)chain * NBINS + k] = v;
    }
    __syncthreads();

    const float* gp = d_g + b * TPAD;
    const float* cp = d_C + chain * TPAD;
    float*       op = out + (size_t)chain * NBINS + KT;

    if (warp == 0) {
        // ---- consumer ----
        int   nfb[32], ncb[32];
        float wbf[8];
#pragma unroll
        for (int s = 0; s < 32; ++s) {
            nfb[s] = (lane > s) ? __float_as_int(fsnp[FPAD + 250 - lane + s]) : 0;
            ncb[s] = __float_as_int(fsnp[FPAD + 218 + s - lane]);
        }
#pragma unroll
        for (int d = 1; d < 8; ++d) wbf[d] = fsnp[FPAD + 250 - d];

        // initial carry from last 32 initial-window spikes
        float c0 = 0.f, c1 = 0.f, c2 = 0.f, c3 = 0.f;
#pragma unroll
        for (int s = 0; s < 32; s += 4) {
            c0 = fmaf(ip[218 + s],     __int_as_float(ncb[s]),     c0);
            c1 = fmaf(ip[219 + s],     __int_as_float(ncb[s + 1]), c1);
            c2 = fmaf(ip[220 + s],     __int_as_float(ncb[s + 2]), c2);
            c3 = fmaf(ip[221 + s],     __int_as_float(ncb[s + 3]), c3);
        }
        float carry = (c0 + c1) + (c2 + c3);
        __syncthreads();   // ybuf[0] ready

        for (int i = 0; i < NCHUNK; ++i) {
            int t0 = i * 32;
            float v = ybuf[i & 1][lane] + carry;   // negated margin; spike <=> v<0

            unsigned bw = 0u;
            float k0s = 0.f, k1s = 0.f, k2s = 0.f, k3s = 0.f;
#pragma unroll
            for (int grp = 0; grp < 4; ++grp) {
                int u[8];
#pragma unroll
                for (int j = 0; j < 8; ++j)
                    u[j] = __float_as_int(__shfl_sync(0xffffffffu, v, grp * 8 + j));
                int gm[8];
#pragma unroll
                for (int j = 0; j < 8; ++j) {
                    int msk = u[j] >> 31;                 // -1 iff spike
                    gm[j] = msk;
#pragma unroll
                    for (int d = 1; d < 8 - j; ++d) {
                        int cand = __float_as_int(__int_as_float(u[j + d]) + wbf[d]);
                        u[j + d] = (cand & msk) | (u[j + d] & ~msk);
                    }
                }
                int base = grp * 8;
                if (grp < 3) {   // group-3 correction is dead (v unused after)
                    float s0 = __int_as_float(gm[0] & nfb[base])     + __int_as_float(gm[1] & nfb[base + 1]);
                    float s1 = __int_as_float(gm[2] & nfb[base + 2]) + __int_as_float(gm[3] & nfb[base + 3]);
                    float s2 = __int_as_float(gm[4] & nfb[base + 4]) + __int_as_float(gm[5] & nfb[base + 5]);
                    float s3 = __int_as_float(gm[6] & nfb[base + 6]) + __int_as_float(gm[7] & nfb[base + 7]);
                    v += (s0 + s1) + (s2 + s3);
                }
                k0s += __int_as_float(gm[0] & ncb[base])     + __int_as_float(gm[4] & ncb[base + 4]);
                k1s += __int_as_float(gm[1] & ncb[base + 1]) + __int_as_float(gm[5] & ncb[base + 5]);
                k2s += __int_as_float(gm[2] & ncb[base + 2]) + __int_as_float(gm[6] & ncb[base + 6]);
                k3s += __int_as_float(gm[3] & ncb[base + 3]) + __int_as_float(gm[7] & ncb[base + 7]);
                bw |= (gm[0] & (1u << base))       | (gm[1] & (2u << base))
                    | (gm[2] & (4u << base))       | (gm[3] & (8u << base))
                    | (gm[4] & (16u << base))      | (gm[5] & (32u << base))
                    | (gm[6] & (64u << base))      | (gm[7] & (128u << base));
            }
            carry = (k0s + k1s) + (k2s + k3s);

            float spikef = (float)((bw >> lane) & 1u);
            hist[KT + t0 + lane] = spikef;
            if (t0 + lane < TSIM) op[t0 + lane] = spikef;
            __syncthreads();
        }
    } else {
        // ---- producers: ybase[step s of chunk n] = (c - g) + sum_{m>=32} hist*(-f)
        // stride-4 tap split over q = lane>>3, reduced by shfl. Taps in registers.
        int pw = warp - 1;           // 0..3
        int s  = pw * 8 + (lane & 7);
        int q  = lane >> 3;

        float treg[55];
#pragma unroll
        for (int k = 0; k < 55; ++k)
            treg[k] = fsnp[FPAD + 217 - s - q - 4 * k];   // zero-padded outside [0,KT)

        // prologue: chunk 0 (initial window only)
        {
            float gl = 0.f, cl = 0.f;
            if (lane < 8) { gl = __ldg(gp + s); cl = __ldg(cp + s); }
            const float* hp = hist + KT - 1;
            float acc = 0.0f;
#pragma unroll
            for (int k = 0; k < 55; ++k) {
                int m = 32 + q + 4 * k;
                acc = fmaf(hp[-m], treg[k], acc);
            }
            acc += __shfl_xor_sync(0xffffffffu, acc, 8);
            acc += __shfl_xor_sync(0xffffffffu, acc, 16);
            if (lane < 8) ybuf[0][s] = (cl - gl) + acc;
        }
        __syncthreads();

        for (int i = 0; i < NCHUNK; ++i) {
            if (i + 1 < NCHUNK) {
                int n = i + 1;
                float gl = 0.f, cl = 0.f;
                if (lane < 8) { gl = __ldg(gp + 32 * n + s); cl = __ldg(cp + 32 * n + s); }
                const float* hp = hist + KT + 32 * n - 1;
                float acc = 0.0f;
#pragma unroll
                for (int k = 0; k < 55; ++k) {
                    int m = 32 + q + 4 * k;
                    acc = fmaf(hp[-m], treg[k], acc);
                }
                acc += __shfl_xor_sync(0xffffffffu, acc, 8);
                acc += __shfl_xor_sync(0xffffffffu, acc, 16);
                if (lane < 8) ybuf[n & 1][s] = (cl - gl) + acc;
            }
            __syncthreads();
        }
    }
}

// ---------------- launch ----------------
extern "C" void kernel_launch(void* const* d_in, const int* in_sizes, int n_in,
                              void* d_out, int out_size) {
    const float* stim = (const float*)d_in[0];  // (4,2048,4096)
    const float* init = (const float*)d_in[1];  // (4,250)
    const float* spat = (const float*)d_in[2];  // (2048,)
    const float* tc   = (const float*)d_in[3];  // (250,)
    const float* fbf  = (const float*)d_in[4];  // (250,)
    const float* bias = (const float*)d_in[5];  // (1,)
    float* out = (float*)d_out;                 // (4,64,4096) f32

    static cudaStream_t s1 = 0;
    static cudaEvent_t  e0 = 0, e1 = 0;
    if (s1 == 0) {
        cudaStreamCreateWithFlags(&s1, cudaStreamNonBlocking);
        cudaEventCreateWithFlags(&e0, cudaEventDisableTiming);
        cudaEventCreateWithFlags(&e1, cudaEventDisableTiming);
    }

    // fork: k_thresh runs on s1 concurrently with proj+conv on the main stream
    cudaEventRecord(e0, 0);
    cudaStreamWaitEvent(s1, e0, 0);
    dim3 g3(16, 64);
    k_thresh<<<g3, 256, 0, s1>>>();
    cudaEventRecord(e1, s1);

    dim3 g1(32, 16, 4);
    k_proj<<<g1, 128>>>(stim, spat);
    dim3 g2(32, 4);
    k_conv<<<g2, 128>>>(tc, bias);

    // join, then simulate
    cudaStreamWaitEvent(0, e1, 0);
    k_sim<<<NCHAIN, 160>>>(init, fbf, out);
}

// round 13
// speedup vs baseline: 1.5112x; 1.5112x over previous
#include <cuda_runtime.h>
#include <cstdint>
#include <math.h>

// ---------------- problem constants ----------------
#define BATCH   4
#define NPIX    2048
#define NBINS   4096
#define KT      250
#define NREP    64
#define TSIM    3846          // (NBINS - KT + 1) - 1
#define NCHAIN  (BATCH*NREP)  // 256
#define TPAD    3872
#define PCHUNKS 16
#define PPER    (NPIX/PCHUNKS) // 128
#define NCHUNK  ((TSIM + 31) / 32)   // 121
#define FPAD    40

// ---------------- scratch (no allocations allowed) ----------------
__device__ float    d_partial[PCHUNKS][BATCH*NBINS]; // 1 MiB
__device__ float    d_g[BATCH*TPAD];                 // gensig (padding stays 0)
__device__ float    d_C[NCHAIN*TPAD];                // logit thresholds (padding stays 0)

// ---------------- threefry2x32 (JAX constants, 20 rounds) ----------------
__device__ __forceinline__ void tf2x32(uint32_t k0, uint32_t k1,
                                       uint32_t x0, uint32_t x1,
                                       uint32_t &o0, uint32_t &o1) {
    uint32_t k2 = k0 ^ k1 ^ 0x1BD11BDAu;
#define ROTL(v,s) (((v)<<(s))|((v)>>(32-(s))))
#define RND(r) { x0 += x1; x1 = ROTL(x1,(r)); x1 ^= x0; }
    x0 += k0; x1 += k1;
    RND(13) RND(15) RND(26) RND(6)
    x0 += k1; x1 += k2 + 1u;
    RND(17) RND(29) RND(16) RND(24)
    x0 += k2; x1 += k0 + 2u;
    RND(13) RND(15) RND(26) RND(6)
    x0 += k0; x1 += k1 + 3u;
    RND(17) RND(29) RND(16) RND(24)
    x0 += k1; x1 += k2 + 4u;
    RND(13) RND(15) RND(26) RND(6)
    x0 += k2; x1 += k0 + 5u;
    o0 = x0; o1 = x1;
#undef RND
#undef ROTL
}

// ---------------- K1: spatial projection partials ----------------
// float2 per thread: grid (16,16,4) = 1024 blocks, 128 threads. Per-t ascending-p
// order identical to the float4 version -> d_partial bit-identical.
__global__ void k_proj(const float* __restrict__ stim, const float* __restrict__ w) {
    int b  = blockIdx.z;
    int pc = blockIdx.y;
    int t0 = blockIdx.x * 256 + threadIdx.x * 2;
    const float* base = stim + ((size_t)b * NPIX + (size_t)pc * PPER) * NBINS + t0;

    __shared__ float ws[PPER];
    if (threadIdx.x < PPER) ws[threadIdx.x] = w[pc * PPER + threadIdx.x];
    __syncthreads();

    float2 acc = make_float2(0.f, 0.f);
#pragma unroll 16
    for (int p = 0; p < PPER; ++p) {
        float2 v = *(const float2*)(base + (size_t)p * NBINS);
        float  c = ws[p];
        acc.x += c * v.x; acc.y += c * v.y;
    }
    *(float2*)(&d_partial[pc][b * NBINS + t0]) = acc;
}

// ---------------- K2: reduce partials + temporal conv (fp64, 8 accumulators) ----------------
#define CCH 121
__global__ void k_conv(const float* __restrict__ tc, const float* __restrict__ bias) {
    int b  = blockIdx.y;
    int t0 = blockIdx.x * CCH;
    int cnt = min(CCH, TSIM - t0);
    if (cnt <= 0) return;
    int need = cnt + KT - 1;

    __shared__ float sps[CCH + KT];
    __shared__ float tcs[KT + 6];
    for (int i = threadIdx.x; i < need; i += blockDim.x) {
        float s = 0.f;
        int idx = b * NBINS + t0 + i;
#pragma unroll
        for (int pc = 0; pc < PCHUNKS; ++pc) s += d_partial[pc][idx];
        sps[i] = s;
    }
    for (int i = threadIdx.x; i < KT + 6; i += blockDim.x) tcs[i] = (i < KT) ? tc[i] : 0.0f;
    __syncthreads();

    double bs = (double)bias[0];
    for (int t = threadIdx.x; t < cnt; t += blockDim.x) {
        double a[8];
#pragma unroll
        for (int j = 0; j < 8; ++j) a[j] = 0.0;
#pragma unroll 4
        for (int k = 0; k < KT; k += 8) {
#pragma unroll
            for (int j = 0; j < 8; ++j)
                if (k + j < KT) a[j] += (double)sps[t + k + j] * (double)tcs[k + j];
        }
        double s = ((a[0] + a[1]) + (a[2] + a[3])) + ((a[4] + a[5]) + (a[6] + a[7]));
        d_g[b * TPAD + t0 + t] = (float)(s + bs);
    }
}

// ---------------- double-float fp32 log of exact-integer-valued float ----------------
__device__ __forceinline__ void df_logm(float a, float &lh, float &ll, int &e) {
    int ib = __float_as_int(a);
    e = ((ib >> 23) & 0xff) - 127;
    float m = __int_as_float((ib & 0x007fffff) | 0x3f800000);
    if (m > 1.5f) { m *= 0.5f; e += 1; }
    float num = m - 1.0f;
    float dh  = m + 1.0f;
    float bv  = dh - m;
    float dl  = (1.0f - bv) + (m - (dh - bv));
    float q1  = __fdividef(num, dh);
    float rem = fmaf(-q1, dh, num);
    rem       = fmaf(-q1, dl, rem);
    float q2  = __fdividef(rem, dh);
    float sh  = q1 + q2;
    float sl  = q2 - (sh - q1);
    float t = sh * sh;
    float w = fmaf(t, 1.0f/19.0f, 1.0f/17.0f);
    w = fmaf(t, w, 1.0f/15.0f);
    w = fmaf(t, w, 1.0f/13.0f);
    w = fmaf(t, w, 1.0f/11.0f);
    w = fmaf(t, w, 1.0f/9.0f);
    w = fmaf(t, w, 1.0f/7.0f);
    w = fmaf(t, w, 1.0f/5.0f);
    w = fmaf(t, w, 1.0f/3.0f);
    w = w * t;
    float ph = 2.0f * sh, pl = 2.0f * sl;
    float qh = ph * w;
    float ql = fmaf(ph, w, -qh);
    ql = fmaf(pl, w, ql);
    lh = ph + qh;
    ll = ((ph - lh) + qh) + (pl + ql);
}

// ---------------- K3: keys + thresholds fused. c[i][t] = logit(uniform) ----------------
// grid (16, 64), block 256. MUST run immediately before k_sim (d_C L2 locality).
__global__ void k_thresh() {
    int t = blockIdx.x * 256 + threadIdx.x;
    if (t >= TSIM) return;
    uint32_t kk0, kk1;
    tf2x32(0u, 42u, 0u, (uint32_t)t, kk0, kk1);   // split(key(42))[t]
    int i0 = blockIdx.y * 4;
#pragma unroll
    for (int j = 0; j < 4; ++j) {
        int i = i0 + j;
        uint32_t o0, o1;
        tf2x32(kk0, kk1, 0u, (uint32_t)i, o0, o1);
        uint32_t bits = o0 ^ o1;
        uint32_t k = bits >> 9;
        float c;
        if (k == 0u) {
            c = -__int_as_float(0x7f800000);
        } else {
            float a = (float)k;
            float bf = (float)(0x800000u - k);
            float lah, lal; int ea; df_logm(a,  lah, lal, ea);
            float lbh, lbl; int eb; df_logm(bf, lbh, lbl, eb);
            float de = (float)(ea - eb);
            const float L2H = 0.693145751953125f;
            const float L2L = 1.42860682e-6f;
            float s   = lah - lbh;
            float bv2 = s - lah;
            float err = (lah - (s - bv2)) + ((-lbh) - bv2);
            float dl2 = err + (lal - lbl);
            float Eh  = de * L2H;
            float th2 = Eh + s;
            float bv3 = th2 - Eh;
            float err2 = (Eh - (th2 - bv3)) + (s - bv3);
            c = th2 + (err2 + dl2 + de * L2L);
        }
        d_C[i * TPAD + t] = c;
    }
}

// ---------------- K4: simulation (R10-proven) ----------------
// warp 0 = consumer (sign+LOP3 select chain), warps 1-4 = ybase producers.
__global__ void __launch_bounds__(160, 2)
k_sim(const float* __restrict__ initial, const float* __restrict__ fbfilt,
      float* __restrict__ out) {
    int chain = blockIdx.x;          // b*64 + r
    int b     = chain >> 6;
    int tid   = threadIdx.x;
    int lane  = tid & 31;
    int warp  = tid >> 5;

    __shared__ float histbuf[8 + KT + TSIM + 40];
    __shared__ float fsnp[FPAD + 256];     // NEGATED padded feedback filter
    __shared__ float ybuf[2][32];          // double-buffered ybase = c - g + far(negated)

    float* hist = histbuf + 8;
    const float* ip = initial + b * KT;

    for (int k = tid; k < FPAD + 256; k += 160) {
        int i = k - FPAD;
        fsnp[k] = (i >= 0 && i < KT) ? -fbfilt[i] : 0.0f;
    }
    for (int k = tid; k < 8; k += 160) histbuf[k] = 0.0f;
    for (int k = tid; k < KT; k += 160) {
        float v = ip[k];
        hist[k] = v;
        out[(size_t)chain * NBINS + k] = v;
    }
    __syncthreads();

    const float* gp = d_g + b * TPAD;
    const float* cp = d_C + chain * TPAD;
    float*       op = out + (size_t)chain * NBINS + KT;

    if (warp == 0) {
        // ---- consumer ----
        int   nfb[32], ncb[32];
        float wbf[8];
#pragma unroll
        for (int s = 0; s < 32; ++s) {
            nfb[s] = (lane > s) ? __float_as_int(fsnp[FPAD + 250 - lane + s]) : 0;
            ncb[s] = __float_as_int(fsnp[FPAD + 218 + s - lane]);
        }
#pragma unroll
        for (int d = 1; d < 8; ++d) wbf[d] = fsnp[FPAD + 250 - d];

        // initial carry from last 32 initial-window spikes
        float c0 = 0.f, c1 = 0.f, c2 = 0.f, c3 = 0.f;
#pragma unroll
        for (int s = 0; s < 32; s += 4) {
            c0 = fmaf(ip[218 + s],     __int_as_float(ncb[s]),     c0);
            c1 = fmaf(ip[219 + s],     __int_as_float(ncb[s + 1]), c1);
            c2 = fmaf(ip[220 + s],     __int_as_float(ncb[s + 2]), c2);
            c3 = fmaf(ip[221 + s],     __int_as_float(ncb[s + 3]), c3);
        }
        float carry = (c0 + c1) + (c2 + c3);
        __syncthreads();   // ybuf[0] ready

        for (int i = 0; i < NCHUNK; ++i) {
            int t0 = i * 32;
            float v = ybuf[i & 1][lane] + carry;   // negated margin; spike <=> v<0

            unsigned bw = 0u;
            float k0s = 0.f, k1s = 0.f, k2s = 0.f, k3s = 0.f;
#pragma unroll
            for (int grp = 0; grp < 4; ++grp) {
                int u[8];
#pragma unroll
                for (int j = 0; j < 8; ++j)
                    u[j] = __float_as_int(__shfl_sync(0xffffffffu, v, grp * 8 + j));
                int gm[8];
#pragma unroll
                for (int j = 0; j < 8; ++j) {
                    int msk = u[j] >> 31;                 // -1 iff spike
                    gm[j] = msk;
#pragma unroll
                    for (int d = 1; d < 8 - j; ++d) {
                        int cand = __float_as_int(__int_as_float(u[j + d]) + wbf[d]);
                        u[j + d] = (cand & msk) | (u[j + d] & ~msk);
                    }
                }
                int base = grp * 8;
                if (grp < 3) {   // group-3 correction is dead (v unused after)
                    float s0 = __int_as_float(gm[0] & nfb[base])     + __int_as_float(gm[1] & nfb[base + 1]);
                    float s1 = __int_as_float(gm[2] & nfb[base + 2]) + __int_as_float(gm[3] & nfb[base + 3]);
                    float s2 = __int_as_float(gm[4] & nfb[base + 4]) + __int_as_float(gm[5] & nfb[base + 5]);
                    float s3 = __int_as_float(gm[6] & nfb[base + 6]) + __int_as_float(gm[7] & nfb[base + 7]);
                    v += (s0 + s1) + (s2 + s3);
                }
                k0s += __int_as_float(gm[0] & ncb[base])     + __int_as_float(gm[4] & ncb[base + 4]);
                k1s += __int_as_float(gm[1] & ncb[base + 1]) + __int_as_float(gm[5] & ncb[base + 5]);
                k2s += __int_as_float(gm[2] & ncb[base + 2]) + __int_as_float(gm[6] & ncb[base + 6]);
                k3s += __int_as_float(gm[3] & ncb[base + 3]) + __int_as_float(gm[7] & ncb[base + 7]);
                bw |= (gm[0] & (1u << base))       | (gm[1] & (2u << base))
                    | (gm[2] & (4u << base))       | (gm[3] & (8u << base))
                    | (gm[4] & (16u << base))      | (gm[5] & (32u << base))
                    | (gm[6] & (64u << base))      | (gm[7] & (128u << base));
            }
            carry = (k0s + k1s) + (k2s + k3s);

            float spikef = (float)((bw >> lane) & 1u);
            hist[KT + t0 + lane] = spikef;
            if (t0 + lane < TSIM) op[t0 + lane] = spikef;
            __syncthreads();
        }
    } else {
        // ---- producers: ybase[step s of chunk n] = (c - g) + sum_{m>=32} hist*(-f)
        // stride-4 tap split over q = lane>>3, reduced by shfl. Taps in registers.
        int pw = warp - 1;           // 0..3
        int s  = pw * 8 + (lane & 7);
        int q  = lane >> 3;

        float treg[55];
#pragma unroll
        for (int k = 0; k < 55; ++k)
            treg[k] = fsnp[FPAD + 217 - s - q - 4 * k];   // zero-padded outside [0,KT)

        // prologue: chunk 0 (initial window only)
        {
            float gl = 0.f, cl = 0.f;
            if (lane < 8) { gl = __ldg(gp + s); cl = __ldg(cp + s); }
            const float* hp = hist + KT - 1;
            float acc = 0.0f;
#pragma unroll
            for (int k = 0; k < 55; ++k) {
                int m = 32 + q + 4 * k;
                acc = fmaf(hp[-m], treg[k], acc);
            }
            acc += __shfl_xor_sync(0xffffffffu, acc, 8);
            acc += __shfl_xor_sync(0xffffffffu, acc, 16);
            if (lane < 8) ybuf[0][s] = (cl - gl) + acc;
        }
        __syncthreads();

        for (int i = 0; i < NCHUNK; ++i) {
            if (i + 1 < NCHUNK) {
                int n = i + 1;
                float gl = 0.f, cl = 0.f;
                if (lane < 8) { gl = __ldg(gp + 32 * n + s); cl = __ldg(cp + 32 * n + s); }
                const float* hp = hist + KT + 32 * n - 1;
                float acc = 0.0f;
#pragma unroll
                for (int k = 0; k < 55; ++k) {
                    int m = 32 + q + 4 * k;
                    acc = fmaf(hp[-m], treg[k], acc);
                }
                acc += __shfl_xor_sync(0xffffffffu, acc, 8);
                acc += __shfl_xor_sync(0xffffffffu, acc, 16);
                if (lane < 8) ybuf[n & 1][s] = (cl - gl) + acc;
            }
            __syncthreads();
        }
    }
}

// ---------------- launch ----------------
extern "C" void kernel_launch(void* const* d_in, const int* in_sizes, int n_in,
                              void* d_out, int out_size) {
    const float* stim = (const float*)d_in[0];  // (4,2048,4096)
    const float* init = (const float*)d_in[1];  // (4,250)
    const float* spat = (const float*)d_in[2];  // (2048,)
    const float* tc   = (const float*)d_in[3];  // (250,)
    const float* fbf  = (const float*)d_in[4];  // (250,)
    const float* bias = (const float*)d_in[5];  // (1,)
    float* out = (float*)d_out;                 // (4,64,4096) f32

    dim3 g1(16, 16, 4);
    k_proj<<<g1, 128>>>(stim, spat);
    dim3 g2(32, 4);
    k_conv<<<g2, 128>>>(tc, bias);
    dim3 g3(16, 64);
    k_thresh<<<g3, 256>>>();          // keep last: d_C must be L2-hot for k_sim
    k_sim<<<NCHAIN, 160>>>(init, fbf, out);
}

// round 14
// speedup vs baseline: 1.5389x; 1.0183x over previous
#include <cuda_runtime.h>
#include <cstdint>
#include <math.h>

// ---------------- problem constants ----------------
#define BATCH   4
#define NPIX    2048
#define NBINS   4096
#define KT      250
#define NREP    64
#define TSIM    3846          // (NBINS - KT + 1) - 1
#define NCHAIN  (BATCH*NREP)  // 256
#define TPAD    3872
#define PCHUNKS 16
#define PPER    (NPIX/PCHUNKS) // 128
#define NCHUNK  ((TSIM + 31) / 32)   // 121
#define FPAD    40
#define HPAD    10             // histbuf front pad; makes producer float4 blocks 16B-aligned

// ---------------- scratch (no allocations allowed) ----------------
__device__ float    d_partial[PCHUNKS][BATCH*NBINS]; // 1 MiB
__device__ float    d_g[BATCH*TPAD];                 // gensig (padding stays 0)
__device__ float    d_C[NCHAIN*TPAD];                // logit thresholds (padding stays 0)

// ---------------- threefry2x32 (JAX constants, 20 rounds) ----------------
__device__ __forceinline__ void tf2x32(uint32_t k0, uint32_t k1,
                                       uint32_t x0, uint32_t x1,
                                       uint32_t &o0, uint32_t &o1) {
    uint32_t k2 = k0 ^ k1 ^ 0x1BD11BDAu;
#define ROTL(v,s) (((v)<<(s))|((v)>>(32-(s))))
#define RND(r) { x0 += x1; x1 = ROTL(x1,(r)); x1 ^= x0; }
    x0 += k0; x1 += k1;
    RND(13) RND(15) RND(26) RND(6)
    x0 += k1; x1 += k2 + 1u;
    RND(17) RND(29) RND(16) RND(24)
    x0 += k2; x1 += k0 + 2u;
    RND(13) RND(15) RND(26) RND(6)
    x0 += k0; x1 += k1 + 3u;
    RND(17) RND(29) RND(16) RND(24)
    x0 += k1; x1 += k2 + 4u;
    RND(13) RND(15) RND(26) RND(6)
    x0 += k2; x1 += k0 + 5u;
    o0 = x0; o1 = x1;
#undef RND
#undef ROTL
}

// ---------------- K1: spatial projection partials ----------------
__global__ void k_proj(const float* __restrict__ stim, const float* __restrict__ w) {
    int b  = blockIdx.z;
    int pc = blockIdx.y;
    int t0 = blockIdx.x * 256 + threadIdx.x * 2;
    const float* base = stim + ((size_t)b * NPIX + (size_t)pc * PPER) * NBINS + t0;

    __shared__ float ws[PPER];
    if (threadIdx.x < PPER) ws[threadIdx.x] = w[pc * PPER + threadIdx.x];
    __syncthreads();

    float2 acc = make_float2(0.f, 0.f);
#pragma unroll 16
    for (int p = 0; p < PPER; ++p) {
        float2 v = *(const float2*)(base + (size_t)p * NBINS);
        float  c = ws[p];
        acc.x += c * v.x; acc.y += c * v.y;
    }
    *(float2*)(&d_partial[pc][b * NBINS + t0]) = acc;
}

// ---------------- K2: reduce partials + temporal conv (fp64, 8 accumulators) ----------------
#define CCH 121
__global__ void k_conv(const float* __restrict__ tc, const float* __restrict__ bias) {
    int b  = blockIdx.y;
    int t0 = blockIdx.x * CCH;
    int cnt = min(CCH, TSIM - t0);
    if (cnt <= 0) return;
    int need = cnt + KT - 1;

    __shared__ float sps[CCH + KT];
    __shared__ float tcs[KT + 6];
    for (int i = threadIdx.x; i < need; i += blockDim.x) {
        float s = 0.f;
        int idx = b * NBINS + t0 + i;
#pragma unroll
        for (int pc = 0; pc < PCHUNKS; ++pc) s += d_partial[pc][idx];
        sps[i] = s;
    }
    for (int i = threadIdx.x; i < KT + 6; i += blockDim.x) tcs[i] = (i < KT) ? tc[i] : 0.0f;
    __syncthreads();

    double bs = (double)bias[0];
    for (int t = threadIdx.x; t < cnt; t += blockDim.x) {
        double a[8];
#pragma unroll
        for (int j = 0; j < 8; ++j) a[j] = 0.0;
#pragma unroll 4
        for (int k = 0; k < KT; k += 8) {
#pragma unroll
            for (int j = 0; j < 8; ++j)
                if (k + j < KT) a[j] += (double)sps[t + k + j] * (double)tcs[k + j];
        }
        double s = ((a[0] + a[1]) + (a[2] + a[3])) + ((a[4] + a[5]) + (a[6] + a[7]));
        d_g[b * TPAD + t0 + t] = (float)(s + bs);
    }
}

// ---------------- double-float fp32 log of exact-integer-valued float ----------------
__device__ __forceinline__ void df_logm(float a, float &lh, float &ll, int &e) {
    int ib = __float_as_int(a);
    e = ((ib >> 23) & 0xff) - 127;
    float m = __int_as_float((ib & 0x007fffff) | 0x3f800000);
    if (m > 1.5f) { m *= 0.5f; e += 1; }
    float num = m - 1.0f;
    float dh  = m + 1.0f;
    float bv  = dh - m;
    float dl  = (1.0f - bv) + (m - (dh - bv));
    float q1  = __fdividef(num, dh);
    float rem = fmaf(-q1, dh, num);
    rem       = fmaf(-q1, dl, rem);
    float q2  = __fdividef(rem, dh);
    float sh  = q1 + q2;
    float sl  = q2 - (sh - q1);
    float t = sh * sh;
    float w = fmaf(t, 1.0f/19.0f, 1.0f/17.0f);
    w = fmaf(t, w, 1.0f/15.0f);
    w = fmaf(t, w, 1.0f/13.0f);
    w = fmaf(t, w, 1.0f/11.0f);
    w = fmaf(t, w, 1.0f/9.0f);
    w = fmaf(t, w, 1.0f/7.0f);
    w = fmaf(t, w, 1.0f/5.0f);
    w = fmaf(t, w, 1.0f/3.0f);
    w = w * t;
    float ph = 2.0f * sh, pl = 2.0f * sl;
    float qh = ph * w;
    float ql = fmaf(ph, w, -qh);
    ql = fmaf(pl, w, ql);
    lh = ph + qh;
    ll = ((ph - lh) + qh) + (pl + ql);
}

// ---------------- K3: keys + thresholds fused. c[i][t] = logit(uniform) ----------------
// grid (16, 64), block 256. MUST run immediately before k_sim (d_C L2 locality).
__global__ void k_thresh() {
    int t = blockIdx.x * 256 + threadIdx.x;
    if (t >= TSIM) return;
    uint32_t kk0, kk1;
    tf2x32(0u, 42u, 0u, (uint32_t)t, kk0, kk1);   // split(key(42))[t]
    int i0 = blockIdx.y * 4;
#pragma unroll
    for (int j = 0; j < 4; ++j) {
        int i = i0 + j;
        uint32_t o0, o1;
        tf2x32(kk0, kk1, 0u, (uint32_t)i, o0, o1);
        uint32_t bits = o0 ^ o1;
        uint32_t k = bits >> 9;
        float c;
        if (k == 0u) {
            c = -__int_as_float(0x7f800000);
        } else {
            float a = (float)k;
            float bf = (float)(0x800000u - k);
            float lah, lal; int ea; df_logm(a,  lah, lal, ea);
            float lbh, lbl; int eb; df_logm(bf, lbh, lbl, eb);
            float de = (float)(ea - eb);
            const float L2H = 0.693145751953125f;
            const float L2L = 1.42860682e-6f;
            float s   = lah - lbh;
            float bv2 = s - lah;
            float err = (lah - (s - bv2)) + ((-lbh) - bv2);
            float dl2 = err + (lal - lbl);
            float Eh  = de * L2H;
            float th2 = Eh + s;
            float bv3 = th2 - Eh;
            float err2 = (Eh - (th2 - bv3)) + (s - bv3);
            c = th2 + (err2 + dl2 + de * L2L);
        }
        d_C[i * TPAD + t] = c;
    }
}

// ---------------- K4: simulation ----------------
// warp 0 = consumer (sign+LOP3 select chain), warps 1-4 = ybase producers.
// Producers: contiguous 56-tap blocks per q -> 14 aligned LDS.128 per chunk.
__global__ void __launch_bounds__(160, 2)
k_sim(const float* __restrict__ initial, const float* __restrict__ fbfilt,
      float* __restrict__ out) {
    int chain = blockIdx.x;          // b*64 + r
    int b     = chain >> 6;
    int tid   = threadIdx.x;
    int lane  = tid & 31;
    int warp  = tid >> 5;

    __shared__ __align__(16) float histbuf[HPAD + KT + TSIM + 40];
    __shared__ float fsnp[FPAD + 256];     // NEGATED padded feedback filter
    __shared__ float ybuf[2][32];          // double-buffered ybase = c - g + far(negated)

    float* hist = histbuf + HPAD;          // hist[k]: k in [0,KT) initial, KT+t sim spikes
    const float* ip = initial + b * KT;

    for (int k = tid; k < FPAD + 256; k += 160) {
        int i = k - FPAD;
        fsnp[k] = (i >= 0 && i < KT) ? -fbfilt[i] : 0.0f;
    }
    for (int k = tid; k < HPAD; k += 160) histbuf[k] = 0.0f;
    for (int k = tid; k < KT; k += 160) {
        float v = ip[k];
        hist[k] = v;
        out[(size_t)chain * NBINS + k] = v;
    }
    __syncthreads();

    const float* gp = d_g + b * TPAD;
    const float* cp = d_C + chain * TPAD;
    float*       op = out + (size_t)chain * NBINS + KT;

    if (warp == 0) {
        // ---- consumer (unchanged from R13) ----
        int   nfb[32], ncb[32];
        float wbf[8];
#pragma unroll
        for (int s = 0; s < 32; ++s) {
            nfb[s] = (lane > s) ? __float_as_int(fsnp[FPAD + 250 - lane + s]) : 0;
            ncb[s] = __float_as_int(fsnp[FPAD + 218 + s - lane]);
        }
#pragma unroll
        for (int d = 1; d < 8; ++d) wbf[d] = fsnp[FPAD + 250 - d];

        float c0 = 0.f, c1 = 0.f, c2 = 0.f, c3 = 0.f;
#pragma unroll
        for (int s = 0; s < 32; s += 4) {
            c0 = fmaf(ip[218 + s],     __int_as_float(ncb[s]),     c0);
            c1 = fmaf(ip[219 + s],     __int_as_float(ncb[s + 1]), c1);
            c2 = fmaf(ip[220 + s],     __int_as_float(ncb[s + 2]), c2);
            c3 = fmaf(ip[221 + s],     __int_as_float(ncb[s + 3]), c3);
        }
        float carry = (c0 + c1) + (c2 + c3);
        __syncthreads();   // ybuf[0] ready

        for (int i = 0; i < NCHUNK; ++i) {
            int t0 = i * 32;
            float v = ybuf[i & 1][lane] + carry;

            unsigned bw = 0u;
            float k0s = 0.f, k1s = 0.f, k2s = 0.f, k3s = 0.f;
#pragma unroll
            for (int grp = 0; grp < 4; ++grp) {
                int u[8];
#pragma unroll
                for (int j = 0; j < 8; ++j)
                    u[j] = __float_as_int(__shfl_sync(0xffffffffu, v, grp * 8 + j));
                int gm[8];
#pragma unroll
                for (int j = 0; j < 8; ++j) {
                    int msk = u[j] >> 31;
                    gm[j] = msk;
#pragma unroll
                    for (int d = 1; d < 8 - j; ++d) {
                        int cand = __float_as_int(__int_as_float(u[j + d]) + wbf[d]);
                        u[j + d] = (cand & msk) | (u[j + d] & ~msk);
                    }
                }
                int base = grp * 8;
                if (grp < 3) {
                    float s0 = __int_as_float(gm[0] & nfb[base])     + __int_as_float(gm[1] & nfb[base + 1]);
                    float s1 = __int_as_float(gm[2] & nfb[base + 2]) + __int_as_float(gm[3] & nfb[base + 3]);
                    float s2 = __int_as_float(gm[4] & nfb[base + 4]) + __int_as_float(gm[5] & nfb[base + 5]);
                    float s3 = __int_as_float(gm[6] & nfb[base + 6]) + __int_as_float(gm[7] & nfb[base + 7]);
                    v += (s0 + s1) + (s2 + s3);
                }
                k0s += __int_as_float(gm[0] & ncb[base])     + __int_as_float(gm[4] & ncb[base + 4]);
                k1s += __int_as_float(gm[1] & ncb[base + 1]) + __int_as_float(gm[5] & ncb[base + 5]);
                k2s += __int_as_float(gm[2] & ncb[base + 2]) + __int_as_float(gm[6] & ncb[base + 6]);
                k3s += __int_as_float(gm[3] & ncb[base + 3]) + __int_as_float(gm[7] & ncb[base + 7]);
                bw |= (gm[0] & (1u << base))       | (gm[1] & (2u << base))
                    | (gm[2] & (4u << base))       | (gm[3] & (8u << base))
                    | (gm[4] & (16u << base))      | (gm[5] & (32u << base))
                    | (gm[6] & (64u << base))      | (gm[7] & (128u << base));
            }
            carry = (k0s + k1s) + (k2s + k3s);

            float spikef = (float)((bw >> lane) & 1u);
            hist[KT + t0 + lane] = spikef;
            if (t0 + lane < TSIM) op[t0 + lane] = spikef;
            __syncthreads();
        }
    } else {
        // ---- producers: contiguous 56-tap blocks, 14 aligned LDS.128 per chunk ----
        int pw = warp - 1;           // 0..3
        int s  = pw * 8 + (lane & 7);
        int q  = lane >> 3;
        int m0 = 32 + 56 * q;        // taps m in [m0, m0+55]; f zero-padded above 249

        float treg[56];
#pragma unroll
        for (int k = 0; k < 56; ++k)
            treg[k] = fsnp[FPAD + 249 - s - m0 - k];   // zero outside [0,KT)

        // prologue: chunk 0 (reads only initial window + front pad)
        {
            float gl = 0.f, cl = 0.f;
            if (lane < 8) { gl = __ldg(gp + s); cl = __ldg(cp + s); }
            const float4* hp4 = (const float4*)(hist + KT - 56 - m0);
            float a0 = 0.f, a1 = 0.f;
#pragma unroll
            for (int j4 = 0; j4 < 14; ++j4) {
                float4 hv = hp4[j4];
                int j = j4 * 4;
                a0 = fmaf(hv.x, treg[55 - j], a0);
                a1 = fmaf(hv.y, treg[54 - j], a1);
                a0 = fmaf(hv.z, treg[53 - j], a0);
                a1 = fmaf(hv.w, treg[52 - j], a1);
            }
            float acc = a0 + a1;
            acc += __shfl_xor_sync(0xffffffffu, acc, 8);
            acc += __shfl_xor_sync(0xffffffffu, acc, 16);
            if (lane < 8) ybuf[0][s] = (cl - gl) + acc;
        }
        __syncthreads();

        for (int i = 0; i < NCHUNK; ++i) {
            if (i + 1 < NCHUNK) {
                int n = i + 1;
                float gl = 0.f, cl = 0.f;
                if (lane < 8) { gl = __ldg(gp + 32 * n + s); cl = __ldg(cp + 32 * n + s); }
                const float4* hp4 = (const float4*)(hist + KT + 32 * n - 56 - m0);
                float a0 = 0.f, a1 = 0.f;
#pragma unroll
                for (int j4 = 0; j4 < 14; ++j4) {
                    float4 hv = hp4[j4];
                    int j = j4 * 4;
                    a0 = fmaf(hv.x, treg[55 - j], a0);
                    a1 = fmaf(hv.y, treg[54 - j], a1);
                    a0 = fmaf(hv.z, treg[53 - j], a0);
                    a1 = fmaf(hv.w, treg[52 - j], a1);
                }
                float acc = a0 + a1;
                acc += __shfl_xor_sync(0xffffffffu, acc, 8);
                acc += __shfl_xor_sync(0xffffffffu, acc, 16);
                if (lane < 8) ybuf[n & 1][s] = (cl - gl) + acc;
            }
            __syncthreads();
        }
    }
}

// ---------------- launch ----------------
extern "C" void kernel_launch(void* const* d_in, const int* in_sizes, int n_in,
                              void* d_out, int out_size) {
    const float* stim = (const float*)d_in[0];  // (4,2048,4096)
    const float* init = (const float*)d_in[1];  // (4,250)
    const float* spat = (const float*)d_in[2];  // (2048,)
    const float* tc   = (const float*)d_in[3];  // (250,)
    const float* fbf  = (const float*)d_in[4];  // (250,)
    const float* bias = (const float*)d_in[5];  // (1,)
    float* out = (float*)d_out;                 // (4,64,4096) f32

    dim3 g1(16, 16, 4);
    k_proj<<<g1, 128>>>(stim, spat);
    dim3 g2(32, 4);
    k_conv<<<g2, 128>>>(tc, bias);
    dim3 g3(16, 64);
    k_thresh<<<g3, 256>>>();          // keep last: d_C must be L2-hot for k_sim
    k_sim<<<NCHAIN, 160>>>(init, fbf, out);
}